// round 10
// baseline (speedup 1.0000x reference)
#include <cuda_runtime.h>
#include <math.h>

#define T_ 128
#define B_ 128
#define I_ 256
#define H_ 256
#define G4_ 1024
#define NCTA 128

typedef unsigned long long u64;

__device__ unsigned g_slot[NCTA];

__device__ __forceinline__ unsigned ld_acq(const unsigned* p) {
    unsigned v;
    asm volatile("ld.acquire.gpu.global.u32 %0, [%1];" : "=r"(v) : "l"(p) : "memory");
    return v;
}
__device__ __forceinline__ void st_rel(unsigned* p, unsigned v) {
    asm volatile("st.release.gpu.global.u32 [%0], %1;" :: "l"(p), "r"(v) : "memory");
}

// ---------------------------------------------------------------------------
// x-phase: compute this CTA's (32r x 32oc) tile of pre[t2] = x[t2]@Wi[t2]+bi+bh.
// Same split-K 4x(K'=64), 4x4 micro-tile structure as the h-GEMM. Result is
// returned in registers (float4 per thread, mapping (r, oc0)).
// Contains 2 __syncthreads() -- must be called uniformly by all threads.
// ---------------------------------------------------------------------------
__device__ __forceinline__ float4 x_phase(
    const float* __restrict__ xt,  const float* __restrict__ Wit,
    const float* __restrict__ bit, const float* __restrict__ bht,
    float* Xs, float* Wis, float* gred2,
    int tid, int r0, int hc0, int nbase,
    int r, int oc0, int kg, int wi2, int wj2, int kbase)
{
    // fill Wis (gathered gate cols of Wi[t2])
    float4 wv[8];
#pragma unroll
    for (int i = 0; i < 8; ++i) {
        const int s = i * 256 + tid;
        const int k = s >> 3, q = s & 7;
        const int gg = q >> 1, cc = (q & 1) * 4;
        wv[i] = __ldg((const float4*)(Wit + (size_t)k * G4_ + gg * 256 + hc0 + cc));
    }
    // fill Xs (x rows r0..r0+31, k-major, pad 33)
#pragma unroll
    for (int a = 0; a < 4; ++a) {
        const int rr = (tid >> 5) + a * 8;
        const float* src = xt + (size_t)(r0 + rr) * I_;
        float* dst = Xs + rr;
#pragma unroll
        for (int b = 0; b < 8; ++b) {
            const int k = (tid & 31) + b * 32;
            dst[k * 33] = __ldg(src + k);
        }
    }
#pragma unroll
    for (int i = 0; i < 8; ++i) {
        const int s = i * 256 + tid;
        const int k = s >> 3, q = s & 7;
        *(float4*)(Wis + k * 32 + q * 4) = wv[i];
    }
    __syncthreads();

    // GEMM over K'=64
    u64 acc2[4][2];
#pragma unroll
    for (int e = 0; e < 4; ++e) { acc2[e][0] = 0ULL; acc2[e][1] = 0ULL; }
    {
        const float* hq = Xs + wi2 * 4;
        const float* wq = Wis + wj2 * 4;
#pragma unroll 4
        for (int k = 0; k < 64; ++k) {
            const int kk = kbase + k;
            const float* hrow = hq + kk * 33;
            const float h0v = hrow[0], h1v = hrow[1], h2v = hrow[2], h3v = hrow[3];
            ulonglong2 w2 = *(const ulonglong2*)(wq + kk * 32);
            u64 hd;
            asm("mov.b64 %0, {%1, %1};" : "=l"(hd) : "f"(h0v));
            asm("fma.rn.f32x2 %0, %1, %2, %0;" : "+l"(acc2[0][0]) : "l"(hd), "l"(w2.x));
            asm("fma.rn.f32x2 %0, %1, %2, %0;" : "+l"(acc2[0][1]) : "l"(hd), "l"(w2.y));
            asm("mov.b64 %0, {%1, %1};" : "=l"(hd) : "f"(h1v));
            asm("fma.rn.f32x2 %0, %1, %2, %0;" : "+l"(acc2[1][0]) : "l"(hd), "l"(w2.x));
            asm("fma.rn.f32x2 %0, %1, %2, %0;" : "+l"(acc2[1][1]) : "l"(hd), "l"(w2.y));
            asm("mov.b64 %0, {%1, %1};" : "=l"(hd) : "f"(h2v));
            asm("fma.rn.f32x2 %0, %1, %2, %0;" : "+l"(acc2[2][0]) : "l"(hd), "l"(w2.x));
            asm("fma.rn.f32x2 %0, %1, %2, %0;" : "+l"(acc2[2][1]) : "l"(hd), "l"(w2.y));
            asm("mov.b64 %0, {%1, %1};" : "=l"(hd) : "f"(h3v));
            asm("fma.rn.f32x2 %0, %1, %2, %0;" : "+l"(acc2[3][0]) : "l"(hd), "l"(w2.x));
            asm("fma.rn.f32x2 %0, %1, %2, %0;" : "+l"(acc2[3][1]) : "l"(hd), "l"(w2.y));
        }
    }
    // store k-partials
#pragma unroll
    for (int e = 0; e < 4; ++e) {
        float2 p0, p1;
        asm("mov.b64 {%0, %1}, %2;" : "=f"(p0.x), "=f"(p0.y) : "l"(acc2[e][0]));
        asm("mov.b64 {%0, %1}, %2;" : "=f"(p1.x), "=f"(p1.y) : "l"(acc2[e][1]));
        *(float4*)(gred2 + (size_t)(kg * 32 + wi2 * 4 + e) * 36 + wj2 * 4) =
            make_float4(p0.x, p0.y, p1.x, p1.y);
    }
    __syncthreads();

    // reduce + biases
    float4 s = make_float4(0.f, 0.f, 0.f, 0.f);
#pragma unroll
    for (int q = 0; q < 4; ++q) {
        float4 v = *(const float4*)(gred2 + (size_t)(q * 32 + r) * 36 + oc0);
        s.x += v.x; s.y += v.y; s.z += v.z; s.w += v.w;
    }
    const float4 b1 = __ldg((const float4*)(bit + nbase));
    const float4 b2 = __ldg((const float4*)(bht + nbase));
    return make_float4(s.x + b1.x + b2.x, s.y + b1.y + b2.y,
                       s.z + b1.z + b2.z, s.w + b1.w + b2.w);
}

// ---------------------------------------------------------------------------
// Fused persistent kernel: x-projection for step t+1 computed in the barrier
// bubble of step t; pre lives in registers; h-GEMM + cell update as in R5/R8.
// ---------------------------------------------------------------------------
__global__ __launch_bounds__(256, 1) void lstm_scan(
    const float* __restrict__ x,  const float* __restrict__ h0,
    const float* __restrict__ c0, const float* __restrict__ Wi,
    const float* __restrict__ bi, const float* __restrict__ Wh,
    const float* __restrict__ bh,
    float* __restrict__ outputs, float* __restrict__ hfin, float* __restrict__ cfin)
{
    extern __shared__ float smem[];
    float* Hs    = smem;                    // [256][33]
    float* Xs    = Hs  + 256 * 33;          // [256][33]
    float* Whs   = Xs  + 256 * 33;          // [256][32]
    float* Wis   = Whs + 256 * 32;          // [256][32]
    float* gred  = Wis + 256 * 32;          // [4][32][36]
    float* gred2 = gred + 4 * 32 * 36;      // [4][32][36]
    float* gsm   = gred2 + 4 * 32 * 36;     // [32][33]

    const int tid = threadIdx.x;
    const int bid = blockIdx.x;
    const int cg = bid & 31, rg = bid >> 5;
    const int hc0 = cg * 8, r0 = rg * 32;

    const int r  = tid >> 3;
    const int c2 = tid & 7;
    const int oc0 = c2 * 4;
    const int g = oc0 >> 3;
    const int nbase = g * 256 + hc0 + (oc0 & 7);

    const int kg  = tid >> 6;
    const int wi2 = (tid & 63) >> 3;
    const int wj2 = tid & 7;
    const int kbase = kg * 64;

    const unsigned base = g_slot[bid];
    float creg = c0[(r0 + r) * H_ + hc0 + c2];

    // prologue: pre[0] into registers
    float4 pv = x_phase(x, Wi, bi, bh, Xs, Wis, gred2,
                        tid, r0, hc0, nbase, r, oc0, kg, wi2, wj2, kbase);

    for (int t = 0; t < T_; ++t) {
        // --- prefetch Wh[t] gathered cols into Whs (previous readers done) ---
        {
            const float* Wt = Wh + (size_t)t * H_ * G4_;
            float4 wv[8];
#pragma unroll
            for (int i = 0; i < 8; ++i) {
                const int s = i * 256 + tid;
                const int k = s >> 3, q = s & 7;
                const int gg = q >> 1, cc = (q & 1) * 4;
                wv[i] = __ldg((const float4*)(Wt + (size_t)k * G4_ + gg * 256 + hc0 + cc));
            }
#pragma unroll
            for (int i = 0; i < 8; ++i) {
                const int s = i * 256 + tid;
                const int k = s >> 3, q = s & 7;
                *(float4*)(Whs + k * 32 + q * 4) = wv[i];
            }
        }

        // --- x-phase for step t+1 (fills the barrier bubble) ---
        float4 pvnext = make_float4(0.f, 0.f, 0.f, 0.f);
        if (t + 1 < T_) {
            pvnext = x_phase(x + (size_t)(t + 1) * B_ * I_,
                             Wi + (size_t)(t + 1) * I_ * G4_,
                             bi + (size_t)(t + 1) * G4_,
                             bh + (size_t)(t + 1) * G4_,
                             Xs, Wis, gred2,
                             tid, r0, hc0, nbase, r, oc0, kg, wi2, wj2, kbase);
        }

        // --- inter-step barrier: the 32 CTAs of this row group ---
        if (t > 0) {
            if (tid < 32) {
                const unsigned tgt = base + (unsigned)t;
                const unsigned* sl = &g_slot[rg * 32 + tid];
                while (ld_acq(sl) < tgt) __nanosleep(32);
            }
        }
        __syncthreads();

        // --- fill Hs with h[t-1] ---
        const float* hp = (t == 0) ? h0 : (outputs + (size_t)(t - 1) * B_ * H_);
#pragma unroll
        for (int a = 0; a < 4; ++a) {
            const int rr = (tid >> 5) + a * 8;
            const float* src = hp + (size_t)(r0 + rr) * H_;
            float* dst = Hs + rr;
#pragma unroll
            for (int b = 0; b < 8; ++b) {
                const int k = (tid & 31) + b * 32;
                dst[k * 33] = __ldcg(src + k);
            }
        }
        __syncthreads();

        // --- h-GEMM ---
        u64 acc2[4][2];
#pragma unroll
        for (int e = 0; e < 4; ++e) { acc2[e][0] = 0ULL; acc2[e][1] = 0ULL; }
        {
            const float* hq = Hs + wi2 * 4;
            const float* wq = Whs + wj2 * 4;
#pragma unroll 4
            for (int k = 0; k < 64; ++k) {
                const int kk = kbase + k;
                const float* hrow = hq + kk * 33;
                const float h0v = hrow[0], h1v = hrow[1], h2v = hrow[2], h3v = hrow[3];
                ulonglong2 w2 = *(const ulonglong2*)(wq + kk * 32);
                u64 hd;
                asm("mov.b64 %0, {%1, %1};" : "=l"(hd) : "f"(h0v));
                asm("fma.rn.f32x2 %0, %1, %2, %0;" : "+l"(acc2[0][0]) : "l"(hd), "l"(w2.x));
                asm("fma.rn.f32x2 %0, %1, %2, %0;" : "+l"(acc2[0][1]) : "l"(hd), "l"(w2.y));
                asm("mov.b64 %0, {%1, %1};" : "=l"(hd) : "f"(h1v));
                asm("fma.rn.f32x2 %0, %1, %2, %0;" : "+l"(acc2[1][0]) : "l"(hd), "l"(w2.x));
                asm("fma.rn.f32x2 %0, %1, %2, %0;" : "+l"(acc2[1][1]) : "l"(hd), "l"(w2.y));
                asm("mov.b64 %0, {%1, %1};" : "=l"(hd) : "f"(h2v));
                asm("fma.rn.f32x2 %0, %1, %2, %0;" : "+l"(acc2[2][0]) : "l"(hd), "l"(w2.x));
                asm("fma.rn.f32x2 %0, %1, %2, %0;" : "+l"(acc2[2][1]) : "l"(hd), "l"(w2.y));
                asm("mov.b64 %0, {%1, %1};" : "=l"(hd) : "f"(h3v));
                asm("fma.rn.f32x2 %0, %1, %2, %0;" : "+l"(acc2[3][0]) : "l"(hd), "l"(w2.x));
                asm("fma.rn.f32x2 %0, %1, %2, %0;" : "+l"(acc2[3][1]) : "l"(hd), "l"(w2.y));
            }
        }

        // --- store k-partials ---
#pragma unroll
        for (int e = 0; e < 4; ++e) {
            float2 p0, p1;
            asm("mov.b64 {%0, %1}, %2;" : "=f"(p0.x), "=f"(p0.y) : "l"(acc2[e][0]));
            asm("mov.b64 {%0, %1}, %2;" : "=f"(p1.x), "=f"(p1.y) : "l"(acc2[e][1]));
            *(float4*)(gred + (size_t)(kg * 32 + wi2 * 4 + e) * 36 + wj2 * 4) =
                make_float4(p0.x, p0.y, p1.x, p1.y);
        }
        __syncthreads();

        // --- reduce + pre (registers), write gate exchange ---
        {
            float4 s = make_float4(0.f, 0.f, 0.f, 0.f);
#pragma unroll
            for (int q = 0; q < 4; ++q) {
                float4 v = *(const float4*)(gred + (size_t)(q * 32 + r) * 36 + oc0);
                s.x += v.x; s.y += v.y; s.z += v.z; s.w += v.w;
            }
            gsm[r * 33 + oc0 + 0] = s.x + pv.x;
            gsm[r * 33 + oc0 + 1] = s.y + pv.y;
            gsm[r * 33 + oc0 + 2] = s.z + pv.z;
            gsm[r * 33 + oc0 + 3] = s.w + pv.w;
        }
        __syncthreads();

        // --- fused cell update ---
        {
            const float iv = gsm[r * 33 +  0 + c2];
            const float fv = gsm[r * 33 +  8 + c2];
            const float ov = gsm[r * 33 + 16 + c2];
            const float gv = gsm[r * 33 + 24 + c2];
            const float ig = 1.f / (1.f + expf(-iv));
            const float fg = 1.f / (1.f + expf(-fv));
            const float og = 1.f / (1.f + expf(-ov));
            const float gt = tanhf(gv);
            creg = fg * creg + ig * gt;
            const float hn = og * tanhf(creg);
            const int row = r0 + r, col = hc0 + c2;
            outputs[(size_t)t * B_ * H_ + row * H_ + col] = hn;
            if (t == T_ - 1) {
                hfin[row * H_ + col] = hn;
                cfin[row * H_ + col] = creg;
            }
        }

        // --- publish step t ---
        __threadfence();
        __syncthreads();
        if (tid == 0) st_rel(&g_slot[bid], base + (unsigned)(t + 1));

        pv = pvnext;
    }
}

extern "C" void kernel_launch(void* const* d_in, const int* in_sizes, int n_in,
                              void* d_out, int out_size)
{
    (void)in_sizes; (void)n_in; (void)out_size;
    const float* x   = (const float*)d_in[0];
    const float* h0  = (const float*)d_in[1];
    const float* c0  = (const float*)d_in[2];
    const float* Wi  = (const float*)d_in[3];
    const float* bi  = (const float*)d_in[4];
    const float* Wh  = (const float*)d_in[5];
    const float* bh  = (const float*)d_in[6];

    float* out     = (float*)d_out;
    float* outputs = out;
    float* hfin    = out + (size_t)T_ * B_ * H_;
    float* cfin    = hfin + (size_t)B_ * H_;

    // Hs 33792 + Xs 33792 + Whs 32768 + Wis 32768 + gred 18432 + gred2 18432
    // + gsm 4224 = 174208 B
    const int smem_bytes = (256 * 33 * 2 + 256 * 32 * 2 + 4 * 32 * 36 * 2 + 32 * 33) *
                           (int)sizeof(float);
    cudaFuncSetAttribute(lstm_scan, cudaFuncAttributeMaxDynamicSharedMemorySize,
                         smem_bytes);

    lstm_scan<<<NCTA, 256, smem_bytes>>>(x, h0, c0, Wi, bi, Wh, bh,
                                         outputs, hfin, cfin);
}

// round 11
// speedup vs baseline: 1.1788x; 1.1788x over previous
#include <cuda_runtime.h>
#include <math.h>

#define T_ 128
#define B_ 128
#define I_ 256
#define H_ 256
#define G4_ 1024
#define NCTA 128
#define NTHR 384

typedef unsigned long long u64;

__device__ unsigned g_slot[NCTA];

__device__ __forceinline__ unsigned ld_acq(const unsigned* p) {
    unsigned v;
    asm volatile("ld.acquire.gpu.global.u32 %0, [%1];" : "=r"(v) : "l"(p) : "memory");
    return v;
}
__device__ __forceinline__ void st_rel(unsigned* p, unsigned v) {
    asm volatile("st.release.gpu.global.u32 [%0], %1;" :: "l"(p), "r"(v) : "memory");
}

#define BAR_ALL()  asm volatile("bar.sync 0, 384;" ::: "memory")
#define BAR_SCAN() asm volatile("bar.sync 1, 256;" ::: "memory")
#define BAR_X()    asm volatile("bar.sync 2, 128;" ::: "memory")

// SMEM layout (float offsets)
#define OFF_HS    0                     // [256][33]
#define OFF_WHS   (OFF_HS + 256*33)     // [256][32]
#define OFF_GRED  (OFF_WHS + 256*32)    // [4][32][36]
#define OFF_GSM   (OFF_GRED + 4*32*36)  // [32][33]
#define OFF_XS    (OFF_GSM + 32*33)     // [256][33]
#define OFF_WIS   (OFF_XS + 256*33)     // [256][32]
#define OFF_XPART (OFF_WIS + 256*32)    // [2][32][36]
#define OFF_PREB  (OFF_XPART + 2*32*36) // [2][32][36]
#define SMEM_FLTS (OFF_PREB + 2*32*36)

__global__ __launch_bounds__(NTHR, 1) void lstm_fused(
    const float* __restrict__ x,  const float* __restrict__ h0,
    const float* __restrict__ c0, const float* __restrict__ Wi,
    const float* __restrict__ bi, const float* __restrict__ Wh,
    const float* __restrict__ bh,
    float* __restrict__ outputs, float* __restrict__ hfin, float* __restrict__ cfin)
{
    extern __shared__ float smem[];
    float* Hs    = smem + OFF_HS;
    float* Whs   = smem + OFF_WHS;
    float* gred  = smem + OFF_GRED;
    float* gsm   = smem + OFF_GSM;
    float* Xs    = smem + OFF_XS;
    float* Wis   = smem + OFF_WIS;
    float* xpart = smem + OFF_XPART;
    float* preb  = smem + OFF_PREB;

    const int tid = threadIdx.x;
    const int bid = blockIdx.x;
    const int cg = bid & 31, rg = bid >> 5;
    const int hc0 = cg * 8, r0 = rg * 32;

    if (tid < 256) {
        // ================= SCAN GROUP (warps 0-7): R8 scan verbatim ========
        const int r  = tid >> 3;             // 0..31
        const int c2 = tid & 7;              // 0..7
        const int oc0 = c2 * 4;
        const int kg  = tid >> 6;            // 0..3
        const int wi2 = (tid & 63) >> 3;     // 0..7
        const int wj2 = tid & 7;             // 0..7
        const int kbase = kg * 64;

        const unsigned base = g_slot[bid];
        float creg = c0[(r0 + r) * H_ + hc0 + c2];

        BAR_ALL();  // wait for producers' preb[0]

        for (int t = 0; t < T_; ++t) {
            // prefetch Wh[t] gathered cols -> Whs
            {
                const float* Wt = Wh + (size_t)t * H_ * G4_;
                float4 wv[8];
#pragma unroll
                for (int i = 0; i < 8; ++i) {
                    const int s = i * 256 + tid;
                    const int k = s >> 3, q = s & 7;
                    const int gg = q >> 1, cc = (q & 1) * 4;
                    wv[i] = __ldg((const float4*)(Wt + (size_t)k * G4_ + gg * 256 + hc0 + cc));
                }
#pragma unroll
                for (int i = 0; i < 8; ++i) {
                    const int s = i * 256 + tid;
                    const int k = s >> 3, q = s & 7;
                    *(float4*)(Whs + k * 32 + q * 4) = wv[i];
                }
            }

            // inter-step barrier (32 CTAs of this row group)
            if (t > 0) {
                if (tid < 32) {
                    const unsigned tgt = base + (unsigned)t;
                    const unsigned* sl = &g_slot[rg * 32 + tid];
                    while (ld_acq(sl) < tgt) __nanosleep(32);
                }
            }
            BAR_SCAN();

            // fill Hs with h[t-1]
            const float* hp = (t == 0) ? h0 : (outputs + (size_t)(t - 1) * B_ * H_);
#pragma unroll
            for (int a = 0; a < 4; ++a) {
                const int rr = (tid >> 5) + a * 8;
                const float* src = hp + (size_t)(r0 + rr) * H_;
                float* dst = Hs + rr;
#pragma unroll
                for (int b = 0; b < 8; ++b) {
                    const int k = (tid & 31) + b * 32;
                    dst[k * 33] = __ldcg(src + k);
                }
            }
            BAR_SCAN();

            // h-GEMM: 4x4 micro-tile over K'=64
            u64 acc2[4][2];
#pragma unroll
            for (int e = 0; e < 4; ++e) { acc2[e][0] = 0ULL; acc2[e][1] = 0ULL; }
            {
                const float* hq = Hs + wi2 * 4;
                const float* wq = Whs + wj2 * 4;
#pragma unroll 4
                for (int k = 0; k < 64; ++k) {
                    const int kk = kbase + k;
                    const float* hrow = hq + kk * 33;
                    const float h0v = hrow[0], h1v = hrow[1], h2v = hrow[2], h3v = hrow[3];
                    ulonglong2 w2 = *(const ulonglong2*)(wq + kk * 32);
                    u64 hd;
                    asm("mov.b64 %0, {%1, %1};" : "=l"(hd) : "f"(h0v));
                    asm("fma.rn.f32x2 %0, %1, %2, %0;" : "+l"(acc2[0][0]) : "l"(hd), "l"(w2.x));
                    asm("fma.rn.f32x2 %0, %1, %2, %0;" : "+l"(acc2[0][1]) : "l"(hd), "l"(w2.y));
                    asm("mov.b64 %0, {%1, %1};" : "=l"(hd) : "f"(h1v));
                    asm("fma.rn.f32x2 %0, %1, %2, %0;" : "+l"(acc2[1][0]) : "l"(hd), "l"(w2.x));
                    asm("fma.rn.f32x2 %0, %1, %2, %0;" : "+l"(acc2[1][1]) : "l"(hd), "l"(w2.y));
                    asm("mov.b64 %0, {%1, %1};" : "=l"(hd) : "f"(h2v));
                    asm("fma.rn.f32x2 %0, %1, %2, %0;" : "+l"(acc2[2][0]) : "l"(hd), "l"(w2.x));
                    asm("fma.rn.f32x2 %0, %1, %2, %0;" : "+l"(acc2[2][1]) : "l"(hd), "l"(w2.y));
                    asm("mov.b64 %0, {%1, %1};" : "=l"(hd) : "f"(h3v));
                    asm("fma.rn.f32x2 %0, %1, %2, %0;" : "+l"(acc2[3][0]) : "l"(hd), "l"(w2.x));
                    asm("fma.rn.f32x2 %0, %1, %2, %0;" : "+l"(acc2[3][1]) : "l"(hd), "l"(w2.y));
                }
            }
            // store k-partials
#pragma unroll
            for (int e = 0; e < 4; ++e) {
                float2 p0, p1;
                asm("mov.b64 {%0, %1}, %2;" : "=f"(p0.x), "=f"(p0.y) : "l"(acc2[e][0]));
                asm("mov.b64 {%0, %1}, %2;" : "=f"(p1.x), "=f"(p1.y) : "l"(acc2[e][1]));
                *(float4*)(gred + (size_t)(kg * 32 + wi2 * 4 + e) * 36 + wj2 * 4) =
                    make_float4(p0.x, p0.y, p1.x, p1.y);
            }
            BAR_SCAN();

            // reduce + preb[t&1] -> gsm
            {
                float4 s = make_float4(0.f, 0.f, 0.f, 0.f);
#pragma unroll
                for (int q = 0; q < 4; ++q) {
                    float4 v = *(const float4*)(gred + (size_t)(q * 32 + r) * 36 + oc0);
                    s.x += v.x; s.y += v.y; s.z += v.z; s.w += v.w;
                }
                const float4 pv = *(const float4*)(preb + (size_t)(t & 1) * 32 * 36 +
                                                   r * 36 + oc0);
                gsm[r * 33 + oc0 + 0] = s.x + pv.x;
                gsm[r * 33 + oc0 + 1] = s.y + pv.y;
                gsm[r * 33 + oc0 + 2] = s.z + pv.z;
                gsm[r * 33 + oc0 + 3] = s.w + pv.w;
            }
            BAR_SCAN();

            // fused cell update
            {
                const float iv = gsm[r * 33 +  0 + c2];
                const float fv = gsm[r * 33 +  8 + c2];
                const float ov = gsm[r * 33 + 16 + c2];
                const float gv = gsm[r * 33 + 24 + c2];
                const float ig = 1.f / (1.f + expf(-iv));
                const float fg = 1.f / (1.f + expf(-fv));
                const float og = 1.f / (1.f + expf(-ov));
                const float gt = tanhf(gv);
                creg = fg * creg + ig * gt;
                const float hn = og * tanhf(creg);
                const int row = r0 + r, col = hc0 + c2;
                outputs[(size_t)t * B_ * H_ + row * H_ + col] = hn;
                if (t == T_ - 1) {
                    hfin[row * H_ + col] = hn;
                    cfin[row * H_ + col] = creg;
                }
            }

            // publish step t
            __threadfence();
            BAR_SCAN();
            if (tid == 0) st_rel(&g_slot[bid], base + (unsigned)(t + 1));

            BAR_ALL();  // rotate preb double buffer
        }
    } else {
        // ================= PRODUCER GROUP (warps 8-11): pre tiles ==========
        const int xtid = tid - 256;          // 0..127
        const int kg2  = xtid >> 6;          // 0..1
        const int wi2x = (xtid & 63) >> 3;   // 0..7
        const int wj2x = xtid & 7;           // 0..7
        const int kb2  = kg2 * 128;
        const int r2   = xtid >> 2;          // 0..31 (reduce mapping)
        const int q4   = xtid & 3;           // gate index for reduce

        // x_step lambda-equivalent: compute pre[t2] tile into preb[t2&1]
        auto x_step = [&](int t2) {
            const float* xt  = x  + (size_t)t2 * B_ * I_;
            const float* Wit = Wi + (size_t)t2 * I_ * G4_;

            BAR_X();  // prior GEMM reads of Xs/Wis complete
            // fill Xs: 32 rows x 256 k (k-major, pad 33)
#pragma unroll
            for (int a = 0; a < 8; ++a) {
                const int rr = (xtid >> 5) + a * 4;
                const float* src = xt + (size_t)(r0 + rr) * I_;
                float* dst = Xs + rr;
#pragma unroll
                for (int b = 0; b < 8; ++b) {
                    const int k = (xtid & 31) + b * 32;
                    dst[k * 33] = __ldg(src + k);
                }
            }
            // fill Wis: gathered gate cols (16 float4 per thread)
#pragma unroll
            for (int i = 0; i < 16; ++i) {
                const int s = i * 128 + xtid;
                const int k = s >> 3, q = s & 7;
                const int gg = q >> 1, cc = (q & 1) * 4;
                *(float4*)(Wis + k * 32 + q * 4) =
                    __ldg((const float4*)(Wit + (size_t)k * G4_ + gg * 256 + hc0 + cc));
            }
            BAR_X();

            // GEMM: 4x4 micro-tile over K'=128, split-K 2
            u64 acc2[4][2];
#pragma unroll
            for (int e = 0; e < 4; ++e) { acc2[e][0] = 0ULL; acc2[e][1] = 0ULL; }
            {
                const float* hq = Xs + wi2x * 4;
                const float* wq = Wis + wj2x * 4;
#pragma unroll 4
                for (int k = 0; k < 128; ++k) {
                    const int kk = kb2 + k;
                    const float* hrow = hq + kk * 33;
                    const float h0v = hrow[0], h1v = hrow[1], h2v = hrow[2], h3v = hrow[3];
                    ulonglong2 w2 = *(const ulonglong2*)(wq + kk * 32);
                    u64 hd;
                    asm("mov.b64 %0, {%1, %1};" : "=l"(hd) : "f"(h0v));
                    asm("fma.rn.f32x2 %0, %1, %2, %0;" : "+l"(acc2[0][0]) : "l"(hd), "l"(w2.x));
                    asm("fma.rn.f32x2 %0, %1, %2, %0;" : "+l"(acc2[0][1]) : "l"(hd), "l"(w2.y));
                    asm("mov.b64 %0, {%1, %1};" : "=l"(hd) : "f"(h1v));
                    asm("fma.rn.f32x2 %0, %1, %2, %0;" : "+l"(acc2[1][0]) : "l"(hd), "l"(w2.x));
                    asm("fma.rn.f32x2 %0, %1, %2, %0;" : "+l"(acc2[1][1]) : "l"(hd), "l"(w2.y));
                    asm("mov.b64 %0, {%1, %1};" : "=l"(hd) : "f"(h2v));
                    asm("fma.rn.f32x2 %0, %1, %2, %0;" : "+l"(acc2[2][0]) : "l"(hd), "l"(w2.x));
                    asm("fma.rn.f32x2 %0, %1, %2, %0;" : "+l"(acc2[2][1]) : "l"(hd), "l"(w2.y));
                    asm("mov.b64 %0, {%1, %1};" : "=l"(hd) : "f"(h3v));
                    asm("fma.rn.f32x2 %0, %1, %2, %0;" : "+l"(acc2[3][0]) : "l"(hd), "l"(w2.x));
                    asm("fma.rn.f32x2 %0, %1, %2, %0;" : "+l"(acc2[3][1]) : "l"(hd), "l"(w2.y));
                }
            }
#pragma unroll
            for (int e = 0; e < 4; ++e) {
                float2 p0, p1;
                asm("mov.b64 {%0, %1}, %2;" : "=f"(p0.x), "=f"(p0.y) : "l"(acc2[e][0]));
                asm("mov.b64 {%0, %1}, %2;" : "=f"(p1.x), "=f"(p1.y) : "l"(acc2[e][1]));
                *(float4*)(xpart + (size_t)(kg2 * 32 + wi2x * 4 + e) * 36 + wj2x * 4) =
                    make_float4(p0.x, p0.y, p1.x, p1.y);
            }
            BAR_X();

            // reduce 2 partials + biases -> preb[t2&1]; thread: row r2, gate q4
            {
                const float* bit = bi + (size_t)t2 * G4_;
                const float* bht = bh + (size_t)t2 * G4_;
                float* pb = preb + (size_t)(t2 & 1) * 32 * 36 + r2 * 36 + q4 * 8;
                const int nb0 = q4 * 256 + hc0;
#pragma unroll
                for (int ch = 0; ch < 2; ++ch) {
                    float4 v0 = *(const float4*)(xpart + (size_t)(0 * 32 + r2) * 36 + q4 * 8 + ch * 4);
                    float4 v1 = *(const float4*)(xpart + (size_t)(1 * 32 + r2) * 36 + q4 * 8 + ch * 4);
                    float4 b1 = __ldg((const float4*)(bit + nb0 + ch * 4));
                    float4 b2 = __ldg((const float4*)(bht + nb0 + ch * 4));
                    *(float4*)(pb + ch * 4) = make_float4(
                        v0.x + v1.x + b1.x + b2.x, v0.y + v1.y + b1.y + b2.y,
                        v0.z + v1.z + b1.z + b2.z, v0.w + v1.w + b1.w + b2.w);
                }
            }
        };

        x_step(0);      // pre[0]
        BAR_ALL();      // matches scan's pre-loop BAR_ALL

        for (int t = 0; t < T_; ++t) {
            if (t + 1 < T_) x_step(t + 1);   // fill the scan's latency bubble
            BAR_ALL();                        // rotate double buffer
        }
    }
}

extern "C" void kernel_launch(void* const* d_in, const int* in_sizes, int n_in,
                              void* d_out, int out_size)
{
    (void)in_sizes; (void)n_in; (void)out_size;
    const float* x   = (const float*)d_in[0];
    const float* h0  = (const float*)d_in[1];
    const float* c0  = (const float*)d_in[2];
    const float* Wi  = (const float*)d_in[3];
    const float* bi  = (const float*)d_in[4];
    const float* Wh  = (const float*)d_in[5];
    const float* bh  = (const float*)d_in[6];

    float* out     = (float*)d_out;
    float* outputs = out;
    float* hfin    = out + (size_t)T_ * B_ * H_;
    float* cfin    = hfin + (size_t)B_ * H_;

    const int smem_bytes = SMEM_FLTS * (int)sizeof(float);  // 174208 B
    cudaFuncSetAttribute(lstm_fused, cudaFuncAttributeMaxDynamicSharedMemorySize,
                         smem_bytes);

    lstm_fused<<<NCTA, NTHR, smem_bytes>>>(x, h0, c0, Wi, bi, Wh, bh,
                                           outputs, hfin, cfin);
}

// round 12
// speedup vs baseline: 1.2164x; 1.0319x over previous
#include <cuda_runtime.h>
#include <math.h>

#define T_ 128
#define B_ 128
#define I_ 256
#define H_ 256
#define G4_ 1024
#define NSCAN 128
#define NPROD 168
#define NTILE (T_ * 128)

typedef unsigned long long u64;

__device__ float g_preact[(size_t)T_ * B_ * G4_];
__device__ unsigned g_slot[NSCAN];
__device__ unsigned g_pre_flag[NTILE];

__device__ __forceinline__ unsigned ld_acq(const unsigned* p) {
    unsigned v;
    asm volatile("ld.acquire.gpu.global.u32 %0, [%1];" : "=r"(v) : "l"(p) : "memory");
    return v;
}
__device__ __forceinline__ void st_rel(unsigned* p, unsigned v) {
    asm volatile("st.release.gpu.global.u32 [%0], %1;" :: "l"(p), "r"(v) : "memory");
}

// ---------------------------------------------------------------------------
// One kernel, two CTA roles:
//   bid <  128 : persistent scan CTA (R8 scan, plus a 1-thread pre-flag poll)
//   bid >= 128 : producer CTA, grid-strides over the 16384 pre tiles
// __launch_bounds__(256,2): regs<=128 so 2 CTAs co-reside per SM.
// ---------------------------------------------------------------------------
__global__ __launch_bounds__(256, 2) void lstm_fused(
    const float* __restrict__ x,  const float* __restrict__ h0,
    const float* __restrict__ c0, const float* __restrict__ Wi,
    const float* __restrict__ bi, const float* __restrict__ Wh,
    const float* __restrict__ bh,
    float* __restrict__ outputs, float* __restrict__ hfin, float* __restrict__ cfin)
{
    extern __shared__ float smem[];
    float* Hs   = smem;                        // [256][33]
    float* Ws   = smem + 256 * 33;             // [256][32]
    float* gred = smem + 256 * 33 + 256 * 32;  // [4][32][36]
    float* gsm  = gred + 4 * 32 * 36;          // [32][33]

    const int tid = threadIdx.x;
    const int bid = blockIdx.x;

    // common thread mappings (used by both roles)
    const int r   = tid >> 3;            // 0..31
    const int c2  = tid & 7;             // 0..7
    const int oc0 = c2 * 4;
    const int gte = oc0 >> 3;            // gate index of this float4
    const int kg  = tid >> 6;            // 0..3
    const int wi2 = (tid & 63) >> 3;     // 0..7
    const int wj2 = tid & 7;             // 0..7
    const int kbase = kg * 64;

    if (bid < NSCAN) {
        // ===================== SCAN CTA (R8 verbatim + pre poll) ===========
        const int cg = bid & 31, rg = bid >> 5;
        const int hc0 = cg * 8, r0 = rg * 32;
        const int nbase = gte * 256 + hc0 + (oc0 & 7);

        const unsigned base = g_slot[bid];
        float creg = c0[(r0 + r) * H_ + hc0 + c2];

        for (int t = 0; t < T_; ++t) {
            // prefetch Wh[t] gathered cols -> Ws
            {
                const float* Wt = Wh + (size_t)t * H_ * G4_;
                float4 wv[8];
#pragma unroll
                for (int i = 0; i < 8; ++i) {
                    const int s = i * 256 + tid;
                    const int k = s >> 3, q = s & 7;
                    const int gg = q >> 1, cc = (q & 1) * 4;
                    wv[i] = __ldg((const float4*)(Wt + (size_t)k * G4_ + gg * 256 + hc0 + cc));
                }
#pragma unroll
                for (int i = 0; i < 8; ++i) {
                    const int s = i * 256 + tid;
                    const int k = s >> 3, q = s & 7;
                    *(float4*)(Ws + k * 32 + q * 4) = wv[i];
                }
            }

            // waits: h from row-group peers (32 slots) + own pre tile flag
            if (t > 0) {
                if (tid < 32) {
                    const unsigned tgt = base + (unsigned)t;
                    const unsigned* sl = &g_slot[rg * 32 + tid];
                    while (ld_acq(sl) < tgt) __nanosleep(32);
                }
            }
            if (tid == 32) {
                const unsigned* fl = &g_pre_flag[t * 128 + bid];
                while (ld_acq(fl) == 0u) __nanosleep(32);
            }
            __syncthreads();

            // pre value for this thread (produced by a producer CTA; L2-coherent)
            const float4 pv = __ldcg((const float4*)(g_preact + (size_t)t * B_ * G4_ +
                                                     (size_t)(r0 + r) * G4_ + nbase));

            // fill Hs with h[t-1]
            const float* hp = (t == 0) ? h0 : (outputs + (size_t)(t - 1) * B_ * H_);
#pragma unroll
            for (int a = 0; a < 4; ++a) {
                const int rr = (tid >> 5) + a * 8;
                const float* src = hp + (size_t)(r0 + rr) * H_;
                float* dst = Hs + rr;
#pragma unroll
                for (int b = 0; b < 8; ++b) {
                    const int k = (tid & 31) + b * 32;
                    dst[k * 33] = __ldcg(src + k);
                }
            }
            __syncthreads();

            // h-GEMM: 4x4 micro-tile over K'=64 (packed f32x2)
            u64 acc2[4][2];
#pragma unroll
            for (int e = 0; e < 4; ++e) { acc2[e][0] = 0ULL; acc2[e][1] = 0ULL; }
            {
                const float* hq = Hs + wi2 * 4;
                const float* wq = Ws + wj2 * 4;
#pragma unroll 4
                for (int k = 0; k < 64; ++k) {
                    const int kk = kbase + k;
                    const float* hrow = hq + kk * 33;
                    const float h0v = hrow[0], h1v = hrow[1], h2v = hrow[2], h3v = hrow[3];
                    ulonglong2 w2 = *(const ulonglong2*)(wq + kk * 32);
                    u64 hd;
                    asm("mov.b64 %0, {%1, %1};" : "=l"(hd) : "f"(h0v));
                    asm("fma.rn.f32x2 %0, %1, %2, %0;" : "+l"(acc2[0][0]) : "l"(hd), "l"(w2.x));
                    asm("fma.rn.f32x2 %0, %1, %2, %0;" : "+l"(acc2[0][1]) : "l"(hd), "l"(w2.y));
                    asm("mov.b64 %0, {%1, %1};" : "=l"(hd) : "f"(h1v));
                    asm("fma.rn.f32x2 %0, %1, %2, %0;" : "+l"(acc2[1][0]) : "l"(hd), "l"(w2.x));
                    asm("fma.rn.f32x2 %0, %1, %2, %0;" : "+l"(acc2[1][1]) : "l"(hd), "l"(w2.y));
                    asm("mov.b64 %0, {%1, %1};" : "=l"(hd) : "f"(h2v));
                    asm("fma.rn.f32x2 %0, %1, %2, %0;" : "+l"(acc2[2][0]) : "l"(hd), "l"(w2.x));
                    asm("fma.rn.f32x2 %0, %1, %2, %0;" : "+l"(acc2[2][1]) : "l"(hd), "l"(w2.y));
                    asm("mov.b64 %0, {%1, %1};" : "=l"(hd) : "f"(h3v));
                    asm("fma.rn.f32x2 %0, %1, %2, %0;" : "+l"(acc2[3][0]) : "l"(hd), "l"(w2.x));
                    asm("fma.rn.f32x2 %0, %1, %2, %0;" : "+l"(acc2[3][1]) : "l"(hd), "l"(w2.y));
                }
            }
            // store k-partials
#pragma unroll
            for (int e = 0; e < 4; ++e) {
                float2 p0, p1;
                asm("mov.b64 {%0, %1}, %2;" : "=f"(p0.x), "=f"(p0.y) : "l"(acc2[e][0]));
                asm("mov.b64 {%0, %1}, %2;" : "=f"(p1.x), "=f"(p1.y) : "l"(acc2[e][1]));
                *(float4*)(gred + (size_t)(kg * 32 + wi2 * 4 + e) * 36 + wj2 * 4) =
                    make_float4(p0.x, p0.y, p1.x, p1.y);
            }
            __syncthreads();

            // reduce + pre -> gsm
            {
                float4 s = make_float4(0.f, 0.f, 0.f, 0.f);
#pragma unroll
                for (int q = 0; q < 4; ++q) {
                    float4 v = *(const float4*)(gred + (size_t)(q * 32 + r) * 36 + oc0);
                    s.x += v.x; s.y += v.y; s.z += v.z; s.w += v.w;
                }
                gsm[r * 33 + oc0 + 0] = s.x + pv.x;
                gsm[r * 33 + oc0 + 1] = s.y + pv.y;
                gsm[r * 33 + oc0 + 2] = s.z + pv.z;
                gsm[r * 33 + oc0 + 3] = s.w + pv.w;
            }
            __syncthreads();

            // fused cell update
            {
                const float iv = gsm[r * 33 +  0 + c2];
                const float fv = gsm[r * 33 +  8 + c2];
                const float ov = gsm[r * 33 + 16 + c2];
                const float gv = gsm[r * 33 + 24 + c2];
                const float ig = 1.f / (1.f + expf(-iv));
                const float fg = 1.f / (1.f + expf(-fv));
                const float og = 1.f / (1.f + expf(-ov));
                const float gt = tanhf(gv);
                creg = fg * creg + ig * gt;
                const float hn = og * tanhf(creg);
                const int row = r0 + r, col = hc0 + c2;
                outputs[(size_t)t * B_ * H_ + row * H_ + col] = hn;
                if (t == T_ - 1) {
                    hfin[row * H_ + col] = hn;
                    cfin[row * H_ + col] = creg;
                }
            }

            // publish step t
            __threadfence();
            __syncthreads();
            if (tid == 0) st_rel(&g_slot[bid], base + (unsigned)(t + 1));
        }
    } else {
        // ===================== PRODUCER CTA: pre tiles =====================
        for (int id = bid - NSCAN; id < NTILE; id += NPROD) {
            const int t  = id >> 7;
            const int wb = id & 127;
            const int cgw = wb & 31, rgw = wb >> 5;
            const int hc0w = cgw * 8, r0w = rgw * 32;
            const int nbw = gte * 256 + hc0w + (oc0 & 7);
            const float* xt  = x  + (size_t)t * B_ * I_;
            const float* Wit = Wi + (size_t)t * I_ * G4_;

            __syncthreads();  // previous iteration's Hs/Ws reads complete

            // fill Xs (Hs buffer): 32 rows x 256 k, k-major pad 33
#pragma unroll
            for (int a = 0; a < 4; ++a) {
                const int rr = (tid >> 5) + a * 8;
                const float* src = xt + (size_t)(r0w + rr) * I_;
                float* dst = Hs + rr;
#pragma unroll
                for (int b = 0; b < 8; ++b) {
                    const int k = (tid & 31) + b * 32;
                    dst[k * 33] = __ldg(src + k);
                }
            }
            // fill Wis (Ws buffer): gathered gate cols of Wi[t]
#pragma unroll
            for (int i = 0; i < 8; ++i) {
                const int s = i * 256 + tid;
                const int k = s >> 3, q = s & 7;
                const int gg = q >> 1, cc = (q & 1) * 4;
                *(float4*)(Ws + k * 32 + q * 4) =
                    __ldg((const float4*)(Wit + (size_t)k * G4_ + gg * 256 + hc0w + cc));
            }
            __syncthreads();

            // x-GEMM: identical structure to the scan h-GEMM
            u64 acc2[4][2];
#pragma unroll
            for (int e = 0; e < 4; ++e) { acc2[e][0] = 0ULL; acc2[e][1] = 0ULL; }
            {
                const float* hq = Hs + wi2 * 4;
                const float* wq = Ws + wj2 * 4;
#pragma unroll 4
                for (int k = 0; k < 64; ++k) {
                    const int kk = kbase + k;
                    const float* hrow = hq + kk * 33;
                    const float h0v = hrow[0], h1v = hrow[1], h2v = hrow[2], h3v = hrow[3];
                    ulonglong2 w2 = *(const ulonglong2*)(wq + kk * 32);
                    u64 hd;
                    asm("mov.b64 %0, {%1, %1};" : "=l"(hd) : "f"(h0v));
                    asm("fma.rn.f32x2 %0, %1, %2, %0;" : "+l"(acc2[0][0]) : "l"(hd), "l"(w2.x));
                    asm("fma.rn.f32x2 %0, %1, %2, %0;" : "+l"(acc2[0][1]) : "l"(hd), "l"(w2.y));
                    asm("mov.b64 %0, {%1, %1};" : "=l"(hd) : "f"(h1v));
                    asm("fma.rn.f32x2 %0, %1, %2, %0;" : "+l"(acc2[1][0]) : "l"(hd), "l"(w2.x));
                    asm("fma.rn.f32x2 %0, %1, %2, %0;" : "+l"(acc2[1][1]) : "l"(hd), "l"(w2.y));
                    asm("mov.b64 %0, {%1, %1};" : "=l"(hd) : "f"(h2v));
                    asm("fma.rn.f32x2 %0, %1, %2, %0;" : "+l"(acc2[2][0]) : "l"(hd), "l"(w2.x));
                    asm("fma.rn.f32x2 %0, %1, %2, %0;" : "+l"(acc2[2][1]) : "l"(hd), "l"(w2.y));
                    asm("mov.b64 %0, {%1, %1};" : "=l"(hd) : "f"(h3v));
                    asm("fma.rn.f32x2 %0, %1, %2, %0;" : "+l"(acc2[3][0]) : "l"(hd), "l"(w2.x));
                    asm("fma.rn.f32x2 %0, %1, %2, %0;" : "+l"(acc2[3][1]) : "l"(hd), "l"(w2.y));
                }
            }
#pragma unroll
            for (int e = 0; e < 4; ++e) {
                float2 p0, p1;
                asm("mov.b64 {%0, %1}, %2;" : "=f"(p0.x), "=f"(p0.y) : "l"(acc2[e][0]));
                asm("mov.b64 {%0, %1}, %2;" : "=f"(p1.x), "=f"(p1.y) : "l"(acc2[e][1]));
                *(float4*)(gred + (size_t)(kg * 32 + wi2 * 4 + e) * 36 + wj2 * 4) =
                    make_float4(p0.x, p0.y, p1.x, p1.y);
            }
            __syncthreads();

            // reduce + biases -> g_preact[t]
            {
                float4 s = make_float4(0.f, 0.f, 0.f, 0.f);
#pragma unroll
                for (int q = 0; q < 4; ++q) {
                    float4 v = *(const float4*)(gred + (size_t)(q * 32 + r) * 36 + oc0);
                    s.x += v.x; s.y += v.y; s.z += v.z; s.w += v.w;
                }
                const float4 b1 = __ldg((const float4*)(bi + (size_t)t * G4_ + nbw));
                const float4 b2 = __ldg((const float4*)(bh + (size_t)t * G4_ + nbw));
                *(float4*)(g_preact + (size_t)t * B_ * G4_ + (size_t)(r0w + r) * G4_ + nbw) =
                    make_float4(s.x + b1.x + b2.x, s.y + b1.y + b2.y,
                                s.z + b1.z + b2.z, s.w + b1.w + b2.w);
            }

            // publish tile
            __threadfence();
            __syncthreads();
            if (tid == 0) st_rel(&g_pre_flag[id], 1u);
        }
    }
}

// Reset the pre flags for the next call (second graph node, runs after).
__global__ void reset_flags() {
    const int i = blockIdx.x * blockDim.x + threadIdx.x;
    if (i < NTILE) g_pre_flag[i] = 0u;
}

extern "C" void kernel_launch(void* const* d_in, const int* in_sizes, int n_in,
                              void* d_out, int out_size)
{
    (void)in_sizes; (void)n_in; (void)out_size;
    const float* x   = (const float*)d_in[0];
    const float* h0  = (const float*)d_in[1];
    const float* c0  = (const float*)d_in[2];
    const float* Wi  = (const float*)d_in[3];
    const float* bi  = (const float*)d_in[4];
    const float* Wh  = (const float*)d_in[5];
    const float* bh  = (const float*)d_in[6];

    float* out     = (float*)d_out;
    float* outputs = out;
    float* hfin    = out + (size_t)T_ * B_ * H_;
    float* cfin    = hfin + (size_t)B_ * H_;

    // Hs 33792 + Ws 32768 + gred 18432 + gsm 4224 = 89216 B (2 CTAs/SM)
    const int smem_bytes = (256 * 33 + 256 * 32 + 4 * 32 * 36 + 32 * 33) *
                           (int)sizeof(float);
    cudaFuncSetAttribute(lstm_fused, cudaFuncAttributeMaxDynamicSharedMemorySize,
                         smem_bytes);

    lstm_fused<<<NSCAN + NPROD, 256, smem_bytes>>>(x, h0, c0, Wi, bi, Wh, bh,
                                                   outputs, hfin, cfin);
    reset_flags<<<(NTILE + 255) / 256, 256>>>();
}

// round 13
// speedup vs baseline: 1.2901x; 1.0606x over previous
#include <cuda_runtime.h>
#include <math.h>

#define T_ 128
#define B_ 128
#define I_ 256
#define H_ 256
#define G4_ 1024
#define NCTA 128

typedef unsigned long long u64;

__device__ float g_preact[(size_t)T_ * B_ * G4_];
__device__ unsigned g_slot[NCTA];

// ---------------------------------------------------------------------------
// Phase 1 (unchanged, measured ~165us): preact[t] = x[t]@Wi[t] + bi + bh.
// ---------------------------------------------------------------------------
__global__ __launch_bounds__(256) void lstm_phase1(
    const float* __restrict__ x, const float* __restrict__ Wi,
    const float* __restrict__ bi, const float* __restrict__ bh,
    float* __restrict__ preact)
{
    __shared__ float As[2][16][128];
    __shared__ float Bs[2][16][128];

    const int t = blockIdx.y, n0 = blockIdx.x * 128, tid = threadIdx.x;
    const int tx = tid & 15, ty = tid >> 4;
    const float* xA = x + (size_t)t * (B_ * I_);
    const float* WB = Wi + (size_t)t * (I_ * G4_) + n0;
    const int am = tid >> 1, aq = (tid & 1) * 2;
    const int bk = tid >> 4, bn = (tid & 15) * 4;

    u64 acc2[8][4];
#pragma unroll
    for (int i = 0; i < 8; ++i)
#pragma unroll
        for (int j = 0; j < 4; ++j) acc2[i][j] = 0ULL;

    {
        float4 a0 = *(const float4*)(xA + am * I_ + (aq + 0) * 4);
        float4 a1 = *(const float4*)(xA + am * I_ + (aq + 1) * 4);
        As[0][aq * 4 + 0][am] = a0.x; As[0][aq * 4 + 1][am] = a0.y;
        As[0][aq * 4 + 2][am] = a0.z; As[0][aq * 4 + 3][am] = a0.w;
        As[0][aq * 4 + 4][am] = a1.x; As[0][aq * 4 + 5][am] = a1.y;
        As[0][aq * 4 + 6][am] = a1.z; As[0][aq * 4 + 7][am] = a1.w;
        *(float4*)&Bs[0][bk][bn]      = *(const float4*)(WB + (size_t)bk * G4_ + bn);
        *(float4*)&Bs[0][bk][bn + 64] = *(const float4*)(WB + (size_t)bk * G4_ + bn + 64);
    }
    __syncthreads();

    for (int kt = 0; kt < 16; ++kt) {
        const int cur = kt & 1;
        float4 pa0, pa1, pb0, pb1;
        if (kt < 15) {
            const int k0 = (kt + 1) * 16;
            pa0 = *(const float4*)(xA + am * I_ + k0 + (aq + 0) * 4);
            pa1 = *(const float4*)(xA + am * I_ + k0 + (aq + 1) * 4);
            pb0 = *(const float4*)(WB + (size_t)(k0 + bk) * G4_ + bn);
            pb1 = *(const float4*)(WB + (size_t)(k0 + bk) * G4_ + bn + 64);
        }
#pragma unroll
        for (int kk = 0; kk < 16; ++kk) {
            float4 a0 = *(float4*)&As[cur][kk][ty * 4];
            float4 a1 = *(float4*)&As[cur][kk][64 + ty * 4];
            ulonglong2 bp0 = *(ulonglong2*)&Bs[cur][kk][tx * 4];
            ulonglong2 bp1 = *(ulonglong2*)&Bs[cur][kk][64 + tx * 4];
            float av[8] = {a0.x, a0.y, a0.z, a0.w, a1.x, a1.y, a1.z, a1.w};
#pragma unroll
            for (int i = 0; i < 8; ++i) {
                u64 ad;
                asm("mov.b64 %0, {%1, %1};" : "=l"(ad) : "f"(av[i]));
                asm("fma.rn.f32x2 %0, %1, %2, %0;" : "+l"(acc2[i][0]) : "l"(ad), "l"(bp0.x));
                asm("fma.rn.f32x2 %0, %1, %2, %0;" : "+l"(acc2[i][1]) : "l"(ad), "l"(bp0.y));
                asm("fma.rn.f32x2 %0, %1, %2, %0;" : "+l"(acc2[i][2]) : "l"(ad), "l"(bp1.x));
                asm("fma.rn.f32x2 %0, %1, %2, %0;" : "+l"(acc2[i][3]) : "l"(ad), "l"(bp1.y));
            }
        }
        if (kt < 15) {
            const int nb = cur ^ 1;
            As[nb][aq * 4 + 0][am] = pa0.x; As[nb][aq * 4 + 1][am] = pa0.y;
            As[nb][aq * 4 + 2][am] = pa0.z; As[nb][aq * 4 + 3][am] = pa0.w;
            As[nb][aq * 4 + 4][am] = pa1.x; As[nb][aq * 4 + 5][am] = pa1.y;
            As[nb][aq * 4 + 6][am] = pa1.z; As[nb][aq * 4 + 7][am] = pa1.w;
            *(float4*)&Bs[nb][bk][bn]      = pb0;
            *(float4*)&Bs[nb][bk][bn + 64] = pb1;
            __syncthreads();
        }
    }

    const float* bip = bi + (size_t)t * G4_ + n0;
    const float* bhp = bh + (size_t)t * G4_ + n0;
    float* Cp = preact + (size_t)t * (B_ * G4_) + n0;
    float4 i0 = *(const float4*)(bip + tx * 4);
    float4 h0 = *(const float4*)(bhp + tx * 4);
    float4 i1 = *(const float4*)(bip + 64 + tx * 4);
    float4 h1 = *(const float4*)(bhp + 64 + tx * 4);
    float bs[8] = {i0.x + h0.x, i0.y + h0.y, i0.z + h0.z, i0.w + h0.w,
                   i1.x + h1.x, i1.y + h1.y, i1.z + h1.z, i1.w + h1.w};
#pragma unroll
    for (int i = 0; i < 8; ++i) {
        const int m = (i < 4) ? (ty * 4 + i) : (64 + ty * 4 + (i - 4));
        float a[8];
#pragma unroll
        for (int j = 0; j < 4; ++j)
            asm("mov.b64 {%0, %1}, %2;" : "=f"(a[j * 2]), "=f"(a[j * 2 + 1]) : "l"(acc2[i][j]));
        float4 v0 = make_float4(a[0] + bs[0], a[1] + bs[1], a[2] + bs[2], a[3] + bs[3]);
        float4 v1 = make_float4(a[4] + bs[4], a[5] + bs[5], a[6] + bs[6], a[7] + bs[7]);
        *(float4*)(Cp + (size_t)m * G4_ + tx * 4)      = v0;
        *(float4*)(Cp + (size_t)m * G4_ + 64 + tx * 4) = v1;
    }
}

// ---------------------------------------------------------------------------
// Persistent scan with PER-K-GROUP dependencies: k-group kg (warps 2kg,2kg+1)
// only needs h cols [64kg,64kg+64) = the publishes of 8 specific CTAs. Each kg
// polls its own 8 slots, fills its own Hs/Ws rows, and GEMMs independently;
// k-groups overlap each other and straggler producers. 2 full bars/step.
// Cell update reads gate partials directly from gred (no gsm exchange).
// ---------------------------------------------------------------------------
__device__ __forceinline__ unsigned ld_acq(const unsigned* p) {
    unsigned v;
    asm volatile("ld.acquire.gpu.global.u32 %0, [%1];" : "=r"(v) : "l"(p) : "memory");
    return v;
}
__device__ __forceinline__ void st_rel(unsigned* p, unsigned v) {
    asm volatile("st.release.gpu.global.u32 [%0], %1;" :: "l"(p), "r"(v) : "memory");
}
#define BAR_FULL() asm volatile("bar.sync 0, 256;" ::: "memory")
#define BAR_KG(id) asm volatile("bar.sync %0, 64;" :: "r"((id) + 1) : "memory")

__global__ __launch_bounds__(256, 1) void lstm_scan(
    const float* __restrict__ h0, const float* __restrict__ c0,
    const float* __restrict__ Wh,   // [T][H][4H]
    const float* __restrict__ pre,  // [T][B][4H]
    float* __restrict__ outputs,    // [T][B][H]
    float* __restrict__ hfin, float* __restrict__ cfin)
{
    extern __shared__ float smem[];
    float* Hs   = smem;                        // [256 k][33]
    float* Ws   = smem + 256 * 33;             // [256 k][32]
    float* gred = smem + 256 * 33 + 256 * 32;  // [4 kg][32 r][36]

    const int tid = threadIdx.x;
    const int bid = blockIdx.x;
    const int cg = bid & 31, rg = bid >> 5;
    const int hc0 = cg * 8, r0 = rg * 32;

    // GEMM / k-group mapping
    const int kg   = tid >> 6;           // 0..3
    const int ltid = tid & 63;           // 0..63 within k-group pair
    const int wi2  = ltid >> 3;          // 0..7 -> rows wi2*4..+3
    const int wj2  = tid & 7;            // 0..7 -> cols wj2*4..+3
    const int kbase = kg * 64;
    const int myk  = kbase + ltid;       // this thread's Hs k-row to fill

    // cell/epilogue mapping
    const int r  = tid >> 3;             // 0..31
    const int c2 = tid & 7;              // 0..7

    const unsigned base = g_slot[bid];
    float creg = c0[(r0 + r) * H_ + hc0 + c2];

    for (int t = 0; t < T_; ++t) {
        const float* Wt = Wh + (size_t)t * H_ * G4_;
        const float* pt = pre + (size_t)t * B_ * G4_ + (size_t)(r0 + r) * G4_;

        // --- Ws fill: own kg's 64 k-rows (weights, h-independent) ---
#pragma unroll
        for (int i = 0; i < 8; ++i) {
            const int s = i * 64 + ltid;          // 0..511 float4 slots
            const int k = kbase + (s >> 3), q = s & 7;
            const int gg = q >> 1, cc = (q & 1) * 4;
            *(float4*)(Ws + k * 32 + q * 4) =
                __ldg((const float4*)(Wt + (size_t)k * G4_ + gg * 256 + hc0 + cc));
        }

        // --- pre prefetch: 4 gate values for (r, c2) ---
        const float pvi = __ldg(pt +   0 + hc0 + c2);
        const float pvf = __ldg(pt + 256 + hc0 + c2);
        const float pvo = __ldg(pt + 512 + hc0 + c2);
        const float pvg = __ldg(pt + 768 + hc0 + c2);

        // --- per-kg wait: only the 8 producers of our h columns ---
        if (t > 0) {
            if (ltid < 8) {
                const unsigned tgt = base + (unsigned)t;
                const unsigned* sl = &g_slot[rg * 32 + kg * 8 + ltid];
                while (ld_acq(sl) < tgt) __nanosleep(32);
            }
        }
        BAR_KG(kg);

        // --- Hs fill: own kg's 64 k-rows of h[t-1] (coalesced LDG) ---
        {
            const float* hp = (t == 0) ? h0 : (outputs + (size_t)(t - 1) * B_ * H_);
            const float* src = hp + myk;
            float* dst = Hs + myk * 33;
#pragma unroll
            for (int rr = 0; rr < 32; ++rr)
                dst[rr] = __ldcg(src + (size_t)(r0 + rr) * H_);
        }
        BAR_KG(kg);

        // --- GEMM: 4x4 micro-tile over own K'=64 (packed f32x2) ---
        u64 acc2[4][2];
#pragma unroll
        for (int e = 0; e < 4; ++e) { acc2[e][0] = 0ULL; acc2[e][1] = 0ULL; }
        {
            const float* hq = Hs + wi2 * 4;
            const float* wq = Ws + wj2 * 4;
#pragma unroll 4
            for (int k = 0; k < 64; ++k) {
                const int kk = kbase + k;
                const float* hrow = hq + kk * 33;
                const float h0v = hrow[0], h1v = hrow[1], h2v = hrow[2], h3v = hrow[3];
                ulonglong2 w2 = *(const ulonglong2*)(wq + kk * 32);
                u64 hd;
                asm("mov.b64 %0, {%1, %1};" : "=l"(hd) : "f"(h0v));
                asm("fma.rn.f32x2 %0, %1, %2, %0;" : "+l"(acc2[0][0]) : "l"(hd), "l"(w2.x));
                asm("fma.rn.f32x2 %0, %1, %2, %0;" : "+l"(acc2[0][1]) : "l"(hd), "l"(w2.y));
                asm("mov.b64 %0, {%1, %1};" : "=l"(hd) : "f"(h1v));
                asm("fma.rn.f32x2 %0, %1, %2, %0;" : "+l"(acc2[1][0]) : "l"(hd), "l"(w2.x));
                asm("fma.rn.f32x2 %0, %1, %2, %0;" : "+l"(acc2[1][1]) : "l"(hd), "l"(w2.y));
                asm("mov.b64 %0, {%1, %1};" : "=l"(hd) : "f"(h2v));
                asm("fma.rn.f32x2 %0, %1, %2, %0;" : "+l"(acc2[2][0]) : "l"(hd), "l"(w2.x));
                asm("fma.rn.f32x2 %0, %1, %2, %0;" : "+l"(acc2[2][1]) : "l"(hd), "l"(w2.y));
                asm("mov.b64 %0, {%1, %1};" : "=l"(hd) : "f"(h3v));
                asm("fma.rn.f32x2 %0, %1, %2, %0;" : "+l"(acc2[3][0]) : "l"(hd), "l"(w2.x));
                asm("fma.rn.f32x2 %0, %1, %2, %0;" : "+l"(acc2[3][1]) : "l"(hd), "l"(w2.y));
            }
        }
        // store k-partials (row = wi2*4+e within kg slab)
#pragma unroll
        for (int e = 0; e < 4; ++e) {
            float2 p0, p1;
            asm("mov.b64 {%0, %1}, %2;" : "=f"(p0.x), "=f"(p0.y) : "l"(acc2[e][0]));
            asm("mov.b64 {%0, %1}, %2;" : "=f"(p1.x), "=f"(p1.y) : "l"(acc2[e][1]));
            *(float4*)(gred + (size_t)(kg * 32 + wi2 * 4 + e) * 36 + wj2 * 4) =
                make_float4(p0.x, p0.y, p1.x, p1.y);
        }
        BAR_FULL();   // all k-partials visible

        // --- reduce (direct from gred) + pre + fused cell update ---
        {
            float gi = pvi, gf = pvf, go = pvo, gc = pvg;
#pragma unroll
            for (int q = 0; q < 4; ++q) {
                const float* gr = gred + (size_t)(q * 32 + r) * 36;
                gi += gr[ 0 + c2];
                gf += gr[ 8 + c2];
                go += gr[16 + c2];
                gc += gr[24 + c2];
            }
            const float ig = 1.f / (1.f + expf(-gi));
            const float fg = 1.f / (1.f + expf(-gf));
            const float og = 1.f / (1.f + expf(-go));
            const float gt = tanhf(gc);
            creg = fg * creg + ig * gt;
            const float hn = og * tanhf(creg);
            const int row = r0 + r, col = hc0 + c2;
            outputs[(size_t)t * B_ * H_ + row * H_ + col] = hn;
            if (t == T_ - 1) {
                hfin[row * H_ + col] = hn;
                cfin[row * H_ + col] = creg;
            }
        }

        // --- publish step t ---
        __threadfence();
        BAR_FULL();
        if (tid == 0) st_rel(&g_slot[bid], base + (unsigned)(t + 1));
    }
}

extern "C" void kernel_launch(void* const* d_in, const int* in_sizes, int n_in,
                              void* d_out, int out_size)
{
    (void)in_sizes; (void)n_in; (void)out_size;
    const float* x   = (const float*)d_in[0];
    const float* h0  = (const float*)d_in[1];
    const float* c0  = (const float*)d_in[2];
    const float* Wi  = (const float*)d_in[3];
    const float* bi  = (const float*)d_in[4];
    const float* Wh  = (const float*)d_in[5];
    const float* bh  = (const float*)d_in[6];

    float* out     = (float*)d_out;
    float* outputs = out;
    float* hfin    = out + (size_t)T_ * B_ * H_;
    float* cfin    = hfin + (size_t)B_ * H_;

    float* pre;
    cudaGetSymbolAddress((void**)&pre, g_preact);

    // Hs 33792 + Ws 32768 + gred 18432 = 84992 B
    const int smem_bytes = (256 * 33 + 256 * 32 + 4 * 32 * 36) * (int)sizeof(float);
    cudaFuncSetAttribute(lstm_scan, cudaFuncAttributeMaxDynamicSharedMemorySize,
                         smem_bytes);

    dim3 g1(8, T_);
    lstm_phase1<<<g1, 256>>>(x, Wi, bi, bh, pre);

    lstm_scan<<<NCTA, 256, smem_bytes>>>(h0, c0, Wh, pre, outputs, hfin, cfin);
}

// round 15
// speedup vs baseline: 1.4116x; 1.0942x over previous
#include <cuda_runtime.h>
#include <cuda_bf16.h>
#include <math.h>

#define T_ 128
#define B_ 128
#define I_ 256
#define H_ 256
#define G4_ 1024
#define NCTA 128

typedef unsigned long long u64;
typedef unsigned int u32;

__device__ float g_preact[(size_t)T_ * B_ * G4_];
__device__ unsigned g_slot[NCTA];

__device__ __forceinline__ unsigned ld_acq(const unsigned* p) {
    unsigned v;
    asm volatile("ld.acquire.gpu.global.u32 %0, [%1];" : "=r"(v) : "l"(p) : "memory");
    return v;
}
__device__ __forceinline__ void st_rel(unsigned* p, unsigned v) {
    asm volatile("st.release.gpu.global.u32 [%0], %1;" :: "l"(p), "r"(v) : "memory");
}
__device__ __forceinline__ u32 smem_u32(const void* p) {
    u32 a;
    asm("{ .reg .u64 t; cvta.to.shared.u64 t, %1; cvt.u32.u64 %0, t; }"
        : "=r"(a) : "l"(p));
    return a;
}
__device__ __forceinline__ float fast_sig(float x) {
    return __fdividef(1.f, 1.f + __expf(-x));
}
__device__ __forceinline__ float fast_tanh(float x) {
    float a = fminf(fabsf(x), 15.f);
    float e = __expf(2.f * a);
    float r = 1.f - __fdividef(2.f, e + 1.f);
    return copysignf(r, x);
}
__device__ __forceinline__ u32 pack_bf16x2(float lo, float hi) {
    __nv_bfloat162 v = __halves2bfloat162(__float2bfloat16(lo), __float2bfloat16(hi));
    u32 r;
    memcpy(&r, &v, 4);
    return r;
}

// ------------------------- Phase 1 (R8 verbatim, ~165us) -------------------
__global__ __launch_bounds__(256) void lstm_phase1(
    const float* __restrict__ x, const float* __restrict__ Wi,
    const float* __restrict__ bi, const float* __restrict__ bh,
    float* __restrict__ preact)
{
    __shared__ float As[2][16][128];
    __shared__ float Bs[2][16][128];

    const int t = blockIdx.y, n0 = blockIdx.x * 128, tid = threadIdx.x;
    const int tx = tid & 15, ty = tid >> 4;
    const float* xA = x + (size_t)t * (B_ * I_);
    const float* WB = Wi + (size_t)t * (I_ * G4_) + n0;
    const int am = tid >> 1, aq = (tid & 1) * 2;
    const int bk = tid >> 4, bn = (tid & 15) * 4;

    u64 acc2[8][4];
#pragma unroll
    for (int i = 0; i < 8; ++i)
#pragma unroll
        for (int j = 0; j < 4; ++j) acc2[i][j] = 0ULL;

    {
        float4 a0 = *(const float4*)(xA + am * I_ + (aq + 0) * 4);
        float4 a1 = *(const float4*)(xA + am * I_ + (aq + 1) * 4);
        As[0][aq * 4 + 0][am] = a0.x; As[0][aq * 4 + 1][am] = a0.y;
        As[0][aq * 4 + 2][am] = a0.z; As[0][aq * 4 + 3][am] = a0.w;
        As[0][aq * 4 + 4][am] = a1.x; As[0][aq * 4 + 5][am] = a1.y;
        As[0][aq * 4 + 6][am] = a1.z; As[0][aq * 4 + 7][am] = a1.w;
        *(float4*)&Bs[0][bk][bn]      = *(const float4*)(WB + (size_t)bk * G4_ + bn);
        *(float4*)&Bs[0][bk][bn + 64] = *(const float4*)(WB + (size_t)bk * G4_ + bn + 64);
    }
    __syncthreads();

    for (int kt = 0; kt < 16; ++kt) {
        const int cur = kt & 1;
        float4 pa0, pa1, pb0, pb1;
        if (kt < 15) {
            const int k0 = (kt + 1) * 16;
            pa0 = *(const float4*)(xA + am * I_ + k0 + (aq + 0) * 4);
            pa1 = *(const float4*)(xA + am * I_ + k0 + (aq + 1) * 4);
            pb0 = *(const float4*)(WB + (size_t)(k0 + bk) * G4_ + bn);
            pb1 = *(const float4*)(WB + (size_t)(k0 + bk) * G4_ + bn + 64);
        }
#pragma unroll
        for (int kk = 0; kk < 16; ++kk) {
            float4 a0 = *(float4*)&As[cur][kk][ty * 4];
            float4 a1 = *(float4*)&As[cur][kk][64 + ty * 4];
            ulonglong2 bp0 = *(ulonglong2*)&Bs[cur][kk][tx * 4];
            ulonglong2 bp1 = *(ulonglong2*)&Bs[cur][kk][64 + tx * 4];
            float av[8] = {a0.x, a0.y, a0.z, a0.w, a1.x, a1.y, a1.z, a1.w};
#pragma unroll
            for (int i = 0; i < 8; ++i) {
                u64 ad;
                asm("mov.b64 %0, {%1, %1};" : "=l"(ad) : "f"(av[i]));
                asm("fma.rn.f32x2 %0, %1, %2, %0;" : "+l"(acc2[i][0]) : "l"(ad), "l"(bp0.x));
                asm("fma.rn.f32x2 %0, %1, %2, %0;" : "+l"(acc2[i][1]) : "l"(ad), "l"(bp0.y));
                asm("fma.rn.f32x2 %0, %1, %2, %0;" : "+l"(acc2[i][2]) : "l"(ad), "l"(bp1.x));
                asm("fma.rn.f32x2 %0, %1, %2, %0;" : "+l"(acc2[i][3]) : "l"(ad), "l"(bp1.y));
            }
        }
        if (kt < 15) {
            const int nb = cur ^ 1;
            As[nb][aq * 4 + 0][am] = pa0.x; As[nb][aq * 4 + 1][am] = pa0.y;
            As[nb][aq * 4 + 2][am] = pa0.z; As[nb][aq * 4 + 3][am] = pa0.w;
            As[nb][aq * 4 + 4][am] = pa1.x; As[nb][aq * 4 + 5][am] = pa1.y;
            As[nb][aq * 4 + 6][am] = pa1.z; As[nb][aq * 4 + 7][am] = pa1.w;
            *(float4*)&Bs[nb][bk][bn]      = pb0;
            *(float4*)&Bs[nb][bk][bn + 64] = pb1;
            __syncthreads();
        }
    }

    const float* bip = bi + (size_t)t * G4_ + n0;
    const float* bhp = bh + (size_t)t * G4_ + n0;
    float* Cp = preact + (size_t)t * (B_ * G4_) + n0;
    float4 i0 = *(const float4*)(bip + tx * 4);
    float4 h0 = *(const float4*)(bhp + tx * 4);
    float4 i1 = *(const float4*)(bip + 64 + tx * 4);
    float4 h1 = *(const float4*)(bhp + 64 + tx * 4);
    float bs[8] = {i0.x + h0.x, i0.y + h0.y, i0.z + h0.z, i0.w + h0.w,
                   i1.x + h1.x, i1.y + h1.y, i1.z + h1.z, i1.w + h1.w};
#pragma unroll
    for (int i = 0; i < 8; ++i) {
        const int m = (i < 4) ? (ty * 4 + i) : (64 + ty * 4 + (i - 4));
        float a[8];
#pragma unroll
        for (int j = 0; j < 4; ++j)
            asm("mov.b64 {%0, %1}, %2;" : "=f"(a[j * 2]), "=f"(a[j * 2 + 1]) : "l"(acc2[i][j]));
        float4 v0 = make_float4(a[0] + bs[0], a[1] + bs[1], a[2] + bs[2], a[3] + bs[3]);
        float4 v1 = make_float4(a[4] + bs[4], a[5] + bs[5], a[6] + bs[6], a[7] + bs[7]);
        *(float4*)(Cp + (size_t)m * G4_ + tx * 4)      = v0;
        *(float4*)(Cp + (size_t)m * G4_ + 64 + tx * 4) = v1;
    }
}

// ------------------------- HMMA scan ----------------------------------------
// R8 skeleton; GEMM replaced by mma.sync.m16n8k16 bf16 hi/lo (3 passes).
// SMEM byte layout: HsHi[32][264]bf16, HsLo, WsHi[32 n][264 k]bf16, WsLo, gsm.
#define ROWB 528                 // 264 bf16 per row
#define HS_SZ (32 * ROWB)        // 16896
#define OFF_HSHI 0
#define OFF_HSLO (OFF_HSHI + HS_SZ)
#define OFF_WSHI (OFF_HSLO + HS_SZ)
#define OFF_WSLO (OFF_WSHI + HS_SZ)
#define OFF_GSM  (OFF_WSLO + HS_SZ)          // float[32][36]
#define SM_BYTES (OFF_GSM + 32 * 36 * 4)     // 72192

#define MMA_BF16(d0,d1,d2,d3,a0,a1,a2,a3,b0,b1)                              \
    asm volatile("mma.sync.aligned.m16n8k16.row.col.f32.bf16.bf16.f32 "      \
        "{%0,%1,%2,%3}, {%4,%5,%6,%7}, {%8,%9}, {%0,%1,%2,%3};"              \
        : "+f"(d0), "+f"(d1), "+f"(d2), "+f"(d3)                             \
        : "r"(a0), "r"(a1), "r"(a2), "r"(a3), "r"(b0), "r"(b1))

__global__ __launch_bounds__(256, 1) void lstm_scan_mma(
    const float* __restrict__ h0, const float* __restrict__ c0,
    const float* __restrict__ Wh, const float* __restrict__ pre,
    float* __restrict__ outputs, float* __restrict__ hfin, float* __restrict__ cfin)
{
    extern __shared__ char smc[];
    const u32 sb = smem_u32(smc);
    float* gsm = (float*)(smc + OFF_GSM);

    const int tid = threadIdx.x;
    const int bid = blockIdx.x;
    const int cg = bid & 31, rg = bid >> 5;
    const int hc0 = cg * 8, r0 = rg * 32;

    // cell-update mapping
    const int r  = tid >> 3;     // 0..31
    const int c2 = tid & 7;      // 0..7

    // MMA mapping
    const int wid = tid >> 5, lane = tid & 31;
    const int mtile = wid & 1, ntile = wid >> 1;
    const u32 a_off = (u32)((mtile * 16 + (lane & 15)) * ROWB + (lane >> 4) * 16);
    const u32 b_off = (u32)((ntile * 8 + (lane & 7)) * ROWB + ((lane >> 3) & 1) * 16);

    const unsigned base = g_slot[bid];
    float creg = c0[(r0 + r) * H_ + hc0 + c2];

    for (int t = 0; t < T_; ++t) {
        // ---- Ws fill: Wh[t] gathered gate cols -> bf16 hi/lo, n-major ----
        {
            const float* Wt = Wh + (size_t)t * H_ * G4_;
#pragma unroll
            for (int i = 0; i < 8; ++i) {
                const int s = i * 256 + tid;
                const int k = s >> 3, q = s & 7;
                const int g = q >> 1, c4 = (q & 1) * 4;
                float4 v = __ldg((const float4*)(Wt + (size_t)k * G4_ + g * 256 + hc0 + c4));
                const float fv[4] = {v.x, v.y, v.z, v.w};
                const int n0 = g * 8 + c4;
#pragma unroll
                for (int j = 0; j < 4; ++j) {
                    const float f = fv[j];
                    __nv_bfloat16 hb = __float2bfloat16(f);
                    __nv_bfloat16 lb = __float2bfloat16(f - __bfloat162float(hb));
                    const size_t o = (size_t)(n0 + j) * ROWB + (size_t)k * 2;
                    *(__nv_bfloat16*)(smc + OFF_WSHI + o) = hb;
                    *(__nv_bfloat16*)(smc + OFF_WSLO + o) = lb;
                }
            }
        }

        // ---- pre prefetch: 4 gate scalars for (r, c2) ----
        const float* pt = pre + (size_t)t * B_ * G4_ + (size_t)(r0 + r) * G4_;
        const float pvi = __ldg(pt +   0 + hc0 + c2);
        const float pvf = __ldg(pt + 256 + hc0 + c2);
        const float pvo = __ldg(pt + 512 + hc0 + c2);
        const float pvg = __ldg(pt + 768 + hc0 + c2);

        // ---- inter-step barrier: the 32 CTAs of this row group ----
        if (t > 0) {
            if (tid < 32) {
                const unsigned tgt = base + (unsigned)t;
                const unsigned* sl = &g_slot[rg * 32 + tid];
                while (ld_acq(sl) < tgt) __nanosleep(32);
            }
        }
        __syncthreads();

        // ---- Hs fill: h[t-1] fp32 -> bf16 hi/lo, row-major ----
        {
            const float* hp = (t == 0) ? h0 : (outputs + (size_t)(t - 1) * B_ * H_);
#pragma unroll
            for (int a = 0; a < 4; ++a) {
                const int rr = (tid >> 5) + a * 8;
                const float2* src = (const float2*)(hp + (size_t)(r0 + rr) * H_);
#pragma unroll
                for (int b = 0; b < 4; ++b) {
                    const int k2 = (tid & 31) + b * 32;     // float2 index
                    float2 v = __ldcg(src + k2);
                    __nv_bfloat16 h0b = __float2bfloat16(v.x);
                    __nv_bfloat16 h1b = __float2bfloat16(v.y);
                    u32 hw;
                    {
                        __nv_bfloat162 p2 = __halves2bfloat162(h0b, h1b);
                        memcpy(&hw, &p2, 4);
                    }
                    u32 lw = pack_bf16x2(v.x - __bfloat162float(h0b),
                                         v.y - __bfloat162float(h1b));
                    const size_t o = (size_t)rr * ROWB + (size_t)k2 * 4;
                    *(u32*)(smc + OFF_HSHI + o) = hw;
                    *(u32*)(smc + OFF_HSLO + o) = lw;
                }
            }
        }
        __syncthreads();

        // ---- MMA: warp owns (mtile 16 rows) x (ntile 8 cols), K=256 ----
        float d0 = 0.f, d1 = 0.f, d2 = 0.f, d3 = 0.f;
#pragma unroll
        for (int kt = 0; kt < 16; ++kt) {
            const u32 ab = sb + OFF_HSHI + a_off + kt * 32;
            const u32 bb = sb + OFF_WSHI + b_off + kt * 32;
            u32 ah0, ah1, ah2, ah3, al0, al1, al2, al3, bh0, bh1, bl0, bl1;
            asm volatile("ldmatrix.sync.aligned.m8n8.x4.shared.b16 {%0,%1,%2,%3}, [%4];"
                : "=r"(ah0), "=r"(ah1), "=r"(ah2), "=r"(ah3) : "r"(ab));
            asm volatile("ldmatrix.sync.aligned.m8n8.x4.shared.b16 {%0,%1,%2,%3}, [%4];"
                : "=r"(al0), "=r"(al1), "=r"(al2), "=r"(al3) : "r"(ab + HS_SZ));
            asm volatile("ldmatrix.sync.aligned.m8n8.x2.shared.b16 {%0,%1}, [%2];"
                : "=r"(bh0), "=r"(bh1) : "r"(bb));
            asm volatile("ldmatrix.sync.aligned.m8n8.x2.shared.b16 {%0,%1}, [%2];"
                : "=r"(bl0), "=r"(bl1) : "r"(bb + HS_SZ));
            MMA_BF16(d0, d1, d2, d3, ah0, ah1, ah2, ah3, bh0, bh1);
            MMA_BF16(d0, d1, d2, d3, ah0, ah1, ah2, ah3, bl0, bl1);
            MMA_BF16(d0, d1, d2, d3, al0, al1, al2, al3, bh0, bh1);
        }
        // store D fragment to gsm
        {
            const int m = mtile * 16 + (lane >> 2);
            const int n = ntile * 8 + (lane & 3) * 2;
            *(float2*)&gsm[m * 36 + n]       = make_float2(d0, d1);
            *(float2*)&gsm[(m + 8) * 36 + n] = make_float2(d2, d3);
        }
        __syncthreads();

        // ---- fused cell update ----
        {
            const float gi = gsm[r * 36 +  0 + c2] + pvi;
            const float gf = gsm[r * 36 +  8 + c2] + pvf;
            const float go = gsm[r * 36 + 16 + c2] + pvo;
            const float gc = gsm[r * 36 + 24 + c2] + pvg;
            const float ig = fast_sig(gi);
            const float fg = fast_sig(gf);
            const float og = fast_sig(go);
            const float gt = fast_tanh(gc);
            creg = fg * creg + ig * gt;
            const float hn = og * fast_tanh(creg);
            const int row = r0 + r, col = hc0 + c2;
            outputs[(size_t)t * B_ * H_ + row * H_ + col] = hn;
            if (t == T_ - 1) {
                hfin[row * H_ + col] = hn;
                cfin[row * H_ + col] = creg;
            }
        }

        // ---- publish step t ----
        __threadfence();
        __syncthreads();
        if (tid == 0) st_rel(&g_slot[bid], base + (unsigned)(t + 1));
    }
}

extern "C" void kernel_launch(void* const* d_in, const int* in_sizes, int n_in,
                              void* d_out, int out_size)
{
    (void)in_sizes; (void)n_in; (void)out_size;
    const float* x   = (const float*)d_in[0];
    const float* h0  = (const float*)d_in[1];
    const float* c0  = (const float*)d_in[2];
    const float* Wi  = (const float*)d_in[3];
    const float* bi  = (const float*)d_in[4];
    const float* Wh  = (const float*)d_in[5];
    const float* bh  = (const float*)d_in[6];

    float* out     = (float*)d_out;
    float* outputs = out;
    float* hfin    = out + (size_t)T_ * B_ * H_;
    float* cfin    = hfin + (size_t)B_ * H_;

    float* pre;
    cudaGetSymbolAddress((void**)&pre, g_preact);

    cudaFuncSetAttribute(lstm_scan_mma, cudaFuncAttributeMaxDynamicSharedMemorySize,
                         SM_BYTES);

    dim3 g1(8, T_);
    lstm_phase1<<<g1, 256>>>(x, Wi, bi, bh, pre);

    lstm_scan_mma<<<NCTA, 256, SM_BYTES>>>(h0, c0, Wh, pre, outputs, hfin, cfin);
}